// round 2
// baseline (speedup 1.0000x reference)
#include <cuda_runtime.h>

#define Bc 4
#define Nc 8192
#define Cc 64
#define Kc 16
#define BN_SCALE_F 0.9999950000374997f

// folded-weight slab layout (floats), per block — pair-packed for f32x2
#define FOLD_FLOATS 16896
#define OFF_WQ1  0      // 3 j * 64
#define OFF_B1   192
#define OFF_WQ2  256    // 64 j * 64
#define OFF_B2   4352
#define OFF_AQ1  4416
#define OFF_AB1  8512
#define OFF_AQ2  8576
#define OFF_AB2  12672
#define OFF_DQ   12736
#define OFF_DB   16832

#define VSTRIDE 20
#define VWARP   (64*VSTRIDE)   // 1280 floats per warp
#define NWARPS  16
#define MB_OFF  (FOLD_FLOATS + NWARPS*VWARP)            // 37376
#define NB_OFF  (MB_OFF + NWARPS*64)                    // 38400
#define SMEM_FLOATS (NB_OFF + NWARPS*16)                // 38656

typedef unsigned long long u64;

__device__ float  g_fold[2*FOLD_FLOATS];
__device__ float4 g_p4[Bc*Nc];
__device__ float  g_xA[Bc*Nc*Cc];
__device__ float  g_xB[Bc*Nc*Cc];

struct WPtrs { const float* p[20]; };

// ---------------- f32x2 helpers ----------------
__device__ __forceinline__ u64 ffma2(u64 a, u64 b, u64 c) {
  u64 d; asm("fma.rn.f32x2 %0, %1, %2, %3;" : "=l"(d) : "l"(a), "l"(b), "l"(c));
  return d;
}
__device__ __forceinline__ u64 fadd2(u64 a, u64 b) {
  u64 d; asm("add.rn.f32x2 %0, %1, %2;" : "=l"(d) : "l"(a), "l"(b));
  return d;
}
__device__ __forceinline__ u64 pack2(float x, float y) {
  u64 u; asm("mov.b64 %0, {%1, %2};" : "=l"(u) : "f"(x), "f"(y));
  return u;
}
__device__ __forceinline__ float2 unpack2(u64 u) {
  float2 f; asm("mov.b64 {%0, %1}, %2;" : "=f"(f.x), "=f"(f.y) : "l"(u));
  return f;
}

// ---------------- weight folding: BN folded, pair-packed layout ----------------
// pair pi (0..31) = rows (pi, pi+32); owner lane rg = pi&7, slot t = pi>>3
// float offset = OFF + (j*32 + rg*4 + t)*2 + half   (half: 0=row pi, 1=row pi+32)
__device__ __forceinline__ void foldP(float* F, int offW, int offB,
                                      const float* W, const float* bv,
                                      const float* g, const float* be,
                                      int blk, int o, int J) {
  float gs = g[blk*64+o]*BN_SCALE_F;
  int pi = o & 31, half = o >> 5;
  int rg = pi & 7, t = pi >> 3;
  for (int j = 0; j < J; j++)
    F[offW + (j*32 + rg*4 + t)*2 + half] = W[(size_t)blk*64*J + o*J + j]*gs;
  F[offB+o] = bv[blk*64+o]*gs + be[blk*64+o];
}

__global__ void fold_kernel(WPtrs wp) {
  int blk = blockIdx.x, o = threadIdx.x;  // grid 2, block 64
  float* F = g_fold + blk*FOLD_FLOATS;
  foldP(F, OFF_WQ1, OFF_B1,  wp.p[0],  wp.p[1],  wp.p[2],  wp.p[3],  blk, o, 3);
  foldP(F, OFF_WQ2, OFF_B2,  wp.p[4],  wp.p[5],  wp.p[6],  wp.p[7],  blk, o, 64);
  foldP(F, OFF_AQ1, OFF_AB1, wp.p[8],  wp.p[9],  wp.p[10], wp.p[11], blk, o, 64);
  foldP(F, OFF_AQ2, OFF_AB2, wp.p[12], wp.p[13], wp.p[14], wp.p[15], blk, o, 64);
  foldP(F, OFF_DQ,  OFF_DB,  wp.p[16], wp.p[17], wp.p[18], wp.p[19], blk, o, 64);
}

// ---------------- pack p [B,3,N] -> float4 [B*N] ----------------
__global__ void pack_p_kernel(const float* __restrict__ p) {
  int t = blockIdx.x*blockDim.x + threadIdx.x;
  if (t < Bc*Nc) {
    int b = t >> 13, n = t & (Nc-1);
    const float* pb = p + (size_t)b*3*Nc;
    g_p4[t] = make_float4(pb[n], pb[Nc+n], pb[2*Nc+n], 0.f);
  }
}

// ---------------- transpose x [B,C,N] -> [B,N,C] ----------------
__global__ void trans_x_kernel(const float* __restrict__ x) {
  __shared__ float t[32][33];
  int b = blockIdx.z;
  int n0 = blockIdx.x*32, c0 = blockIdx.y*32;
  int tx = threadIdx.x, ty = threadIdx.y;  // 32x8
  for (int i = ty; i < 32; i += 8)
    t[i][tx] = x[(size_t)b*Cc*Nc + (size_t)(c0+i)*Nc + n0 + tx];
  __syncthreads();
  for (int i = ty; i < 32; i += 8)
    g_xA[(size_t)b*Nc*Cc + (size_t)(n0+i)*Cc + c0 + tx] = t[tx][i];
}

// ---------------- matvec: pair-packed f32x2, lane = (kg, rg) ----------------
// acc[t*4+k] = {out[rg+8t][4kg+k], out[rg+8t+32][4kg+k]}
template<int J>
__device__ __forceinline__ void mv2(const float* __restrict__ Wb,
                                    const float* __restrict__ Bv,
                                    const float* __restrict__ vb,
                                    int rg, int kg, u64 acc[16]) {
#pragma unroll
  for (int t = 0; t < 4; t++) {
    u64 bb = pack2(Bv[rg+8*t], Bv[rg+8*t+32]);
    acc[t*4+0] = bb; acc[t*4+1] = bb; acc[t*4+2] = bb; acc[t*4+3] = bb;
  }
#pragma unroll 4
  for (int j = 0; j < J; j++) {
    const ulonglong2* wp = (const ulonglong2*)(Wb + j*64 + rg*8);
    ulonglong2 wA = wp[0];   // pairs t=0,1
    ulonglong2 wB = wp[1];   // pairs t=2,3
    float4 vv = *(const float4*)(vb + j*VSTRIDE + 4*kg);
    u64 d0 = pack2(vv.x, vv.x), d1 = pack2(vv.y, vv.y);
    u64 d2 = pack2(vv.z, vv.z), d3 = pack2(vv.w, vv.w);
    acc[0]  = ffma2(wA.x, d0, acc[0]);  acc[1]  = ffma2(wA.x, d1, acc[1]);
    acc[2]  = ffma2(wA.x, d2, acc[2]);  acc[3]  = ffma2(wA.x, d3, acc[3]);
    acc[4]  = ffma2(wA.y, d0, acc[4]);  acc[5]  = ffma2(wA.y, d1, acc[5]);
    acc[6]  = ffma2(wA.y, d2, acc[6]);  acc[7]  = ffma2(wA.y, d3, acc[7]);
    acc[8]  = ffma2(wB.x, d0, acc[8]);  acc[9]  = ffma2(wB.x, d1, acc[9]);
    acc[10] = ffma2(wB.x, d2, acc[10]); acc[11] = ffma2(wB.x, d3, acc[11]);
    acc[12] = ffma2(wB.y, d0, acc[12]); acc[13] = ffma2(wB.y, d1, acc[13]);
    acc[14] = ffma2(wB.y, d2, acc[14]); acc[15] = ffma2(wB.y, d3, acc[15]);
  }
}

// unpack + (optional relu) + store plain rows to v
template<bool RELU>
__device__ __forceinline__ void stv(float* vb, int rg, int kg, const u64 acc[16]) {
#pragma unroll
  for (int t = 0; t < 4; t++) {
    float2 f0 = unpack2(acc[t*4+0]), f1 = unpack2(acc[t*4+1]);
    float2 f2 = unpack2(acc[t*4+2]), f3 = unpack2(acc[t*4+3]);
    if (RELU) {
      f0.x = fmaxf(f0.x, 0.f); f0.y = fmaxf(f0.y, 0.f);
      f1.x = fmaxf(f1.x, 0.f); f1.y = fmaxf(f1.y, 0.f);
      f2.x = fmaxf(f2.x, 0.f); f2.y = fmaxf(f2.y, 0.f);
      f3.x = fmaxf(f3.x, 0.f); f3.y = fmaxf(f3.y, 0.f);
    }
    *(float4*)(vb + (rg+8*t)*VSTRIDE + 4*kg)    = make_float4(f0.x, f1.x, f2.x, f3.x);
    *(float4*)(vb + (rg+8*t+32)*VSTRIDE + 4*kg) = make_float4(f0.y, f1.y, f2.y, f3.y);
  }
}

// ---------------- fused PT block ----------------
__global__ void __launch_bounds__(512, 1) trblock_kernel(
    const int* __restrict__ idx, int blk, int finalOut, float* __restrict__ dout) {
  const float* __restrict__ xin = blk ? g_xB : g_xA;
  extern __shared__ float S[];
  int tid = threadIdx.x, wid = tid >> 5, lane = tid & 31;
  int rg = lane & 7, kg = lane >> 3;

  const float* F = g_fold + blk*FOLD_FLOATS;
  for (int i = tid; i < FOLD_FLOATS/4; i += 512)
    ((float4*)S)[i] = ((const float4*)F)[i];
  __syncthreads();

  float* v  = S + FOLD_FLOATS + wid*VWARP;
  float* mb = S + MB_OFF + wid*64;
  int*   nb = (int*)(S + NB_OFF) + wid*16;

  for (int pt = blockIdx.x*NWARPS + wid; pt < Bc*Nc; pt += gridDim.x*NWARPS) {
    int b = pt >> 13, n = pt & (Nc-1);
    (void)n;
    __syncwarp();
    if (lane < 16) {
      int j = idx[(size_t)pt*Kc + lane];
      nb[lane] = j;
      float4 pq = g_p4[pt];
      float4 pn = g_p4[(b << 13) + j];
      v[0*VSTRIDE + lane] = pq.x - pn.x;
      v[1*VSTRIDE + lane] = pq.y - pn.y;
      v[2*VSTRIDE + lane] = pq.z - pn.z;
    }
    __syncwarp();

    u64 acc[16];
    // delta layer1 (3 -> 64) + relu
    mv2<3>(S + OFF_WQ1, S + OFF_B1, v, rg, kg, acc);
    __syncwarp(); stv<true>(v, rg, kg, acc); __syncwarp();

    // delta layer2 (64 -> 64), no relu -> pe
    mv2<64>(S + OFF_WQ2, S + OFF_B2, v, rg, kg, acc);

    // u = gx + pe  (gather from transposed x, L2-resident)
    {
      const float* xb = xin + (((size_t)b) << 13)*Cc;
      int j0 = nb[4*kg+0], j1 = nb[4*kg+1], j2 = nb[4*kg+2], j3 = nb[4*kg+3];
      const float* x0 = xb + (size_t)j0*Cc;
      const float* x1 = xb + (size_t)j1*Cc;
      const float* x2 = xb + (size_t)j2*Cc;
      const float* x3 = xb + (size_t)j3*Cc;
#pragma unroll
      for (int t = 0; t < 4; t++) {
        int rl = rg + 8*t;
        acc[t*4+0] = fadd2(acc[t*4+0], pack2(x0[rl], x0[rl+32]));
        acc[t*4+1] = fadd2(acc[t*4+1], pack2(x1[rl], x1[rl+32]));
        acc[t*4+2] = fadd2(acc[t*4+2], pack2(x2[rl], x2[rl+32]));
        acc[t*4+3] = fadd2(acc[t*4+3], pack2(x3[rl], x3[rl+32]));
      }
    }
    __syncwarp(); stv<false>(v, rg, kg, acc); __syncwarp();

    // alpha layer1 + relu
    mv2<64>(S + OFF_AQ1, S + OFF_AB1, v, rg, kg, acc);
    __syncwarp(); stv<true>(v, rg, kg, acc); __syncwarp();

    // alpha layer2; relu fused into max over K
    mv2<64>(S + OFF_AQ2, S + OFF_AB2, v, rg, kg, acc);
    {
      float m[8];
#pragma unroll
      for (int t = 0; t < 4; t++) {
        float2 f0 = unpack2(acc[t*4+0]), f1 = unpack2(acc[t*4+1]);
        float2 f2 = unpack2(acc[t*4+2]), f3 = unpack2(acc[t*4+3]);
        m[t]   = fmaxf(fmaxf(f0.x, f1.x), fmaxf(f2.x, f3.x));
        m[t+4] = fmaxf(fmaxf(f0.y, f1.y), fmaxf(f2.y, f3.y));
      }
#pragma unroll
      for (int i = 0; i < 8; i++)
        m[i] = fmaxf(m[i], __shfl_xor_sync(0xffffffffu, m[i], 8));
#pragma unroll
      for (int i = 0; i < 8; i++)
        m[i] = fmaxf(m[i], __shfl_xor_sync(0xffffffffu, m[i], 16));
      __syncwarp();
      if (kg == 0) {
#pragma unroll
        for (int t = 0; t < 4; t++) {
          mb[rg+8*t]    = fmaxf(m[t], 0.f);
          mb[rg+8*t+32] = fmaxf(m[t+4], 0.f);
        }
      }
      __syncwarp();
    }

    // down projection (64 -> 64): every lane computes full sums (pair-packed)
    u64 od[4];
#pragma unroll
    for (int t = 0; t < 4; t++)
      od[t] = pack2(S[OFF_DB + rg+8*t], S[OFF_DB + rg+8*t+32]);
    {
      const float4* mb4 = (const float4*)mb;
#pragma unroll 4
      for (int j4 = 0; j4 < 16; j4++) {
        float4 m4 = mb4[j4];
        float ms[4] = {m4.x, m4.y, m4.z, m4.w};
#pragma unroll
        for (int s = 0; s < 4; s++) {
          int j = j4*4 + s;
          const ulonglong2* wp = (const ulonglong2*)(S + OFF_DQ + j*64 + rg*8);
          ulonglong2 wA = wp[0], wB = wp[1];
          u64 md = pack2(ms[s], ms[s]);
          od[0] = ffma2(wA.x, md, od[0]);
          od[1] = ffma2(wA.y, md, od[1]);
          od[2] = ffma2(wB.x, md, od[2]);
          od[3] = ffma2(wB.y, md, od[3]);
        }
      }
    }
    __syncwarp();
    if (kg == 0) {
#pragma unroll
      for (int t = 0; t < 4; t++) {
        float2 f = unpack2(od[t]);
        mb[rg+8*t]    = f.x;
        mb[rg+8*t+32] = f.y;
      }
    }
    __syncwarp();

    // residual + output
    {
      const float* xr = xin + (size_t)pt*Cc;
      float r0 = mb[lane]      + xr[lane];
      float r1 = mb[lane+32]   + xr[lane+32];
      if (finalOut) {
        dout[(size_t)b*Cc*Nc + (size_t)lane*Nc + (pt & (Nc-1))]      = r0;
        dout[(size_t)b*Cc*Nc + (size_t)(lane+32)*Nc + (pt & (Nc-1))] = r1;
      } else {
        float* xo = g_xB + (size_t)pt*Cc;
        xo[lane]      = r0;
        xo[lane+32]   = r1;
      }
    }
  }
}

// ---------------- launch ----------------
extern "C" void kernel_launch(void* const* d_in, const int* in_sizes, int n_in,
                              void* d_out, int out_size) {
  const float* p  = (const float*)d_in[0];
  const float* x  = (const float*)d_in[1];
  const int*  idx = (const int*)d_in[2];
  WPtrs w;
  for (int i = 0; i < 20; i++) w.p[i] = (const float*)d_in[3 + i];

  fold_kernel<<<2, 64>>>(w);
  pack_p_kernel<<<(Bc*Nc + 255)/256, 256>>>(p);
  trans_x_kernel<<<dim3(Nc/32, Cc/32, Bc), dim3(32, 8)>>>(x);

  size_t smem = SMEM_FLOATS * sizeof(float);
  cudaFuncSetAttribute(trblock_kernel, cudaFuncAttributeMaxDynamicSharedMemorySize, (int)smem);

  float* dout = (float*)d_out;
  trblock_kernel<<<148, 512, smem>>>(idx, 0, 0, nullptr);
  trblock_kernel<<<148, 512, smem>>>(idx, 1, 1, dout + (size_t)Bc*3*Nc);

  // first output: p passes through unchanged
  cudaMemcpyAsync(d_out, d_in[0], (size_t)Bc*3*Nc*sizeof(float),
                  cudaMemcpyDeviceToDevice);
}

// round 3
// speedup vs baseline: 2.4048x; 2.4048x over previous
#include <cuda_runtime.h>

#define Bc 4
#define Nc 8192
#define Cc 64
#define Kc 16
#define BN_SCALE_F 0.9999950000374997f

// folded-weight slab (floats), per block. Matvec weights in "quad" layout:
// float4 at ((j>>1)*32 + lane)*4 = { W[lane][j], W[lane+32][j], W[lane][j+1], W[lane+32][j+1] }
#define OFF_WQ1  0        // 2 quads * 32 * 4 = 256 (J=3 + zero pad)
#define OFF_B1   256
#define OFF_WQ2  320      // 32 quads * 128 = 4096
#define OFF_B2   4416
#define OFF_AQ1  4480
#define OFF_AB1  8576
#define OFF_AQ2  8640
#define OFF_AB2  12736
#define OFF_DQ   12800
#define OFF_DB   16896
#define FOLD_FLOATS 16960

#define VSTRIDE 20
#define VWARP   (64*VSTRIDE)     // 1280 floats per warp
#define NWARPS  24
#define NB_OFF  (NWARPS*VWARP)   // 30720
#define SMEM_FLOATS (NB_OFF + NWARPS*16)   // 31104 floats = 124.4KB

__device__ float  g_fold[2*FOLD_FLOATS];
__device__ float4 g_p4[Bc*Nc];
__device__ float  g_xA[Bc*Nc*Cc];
__device__ float  g_xB[Bc*Nc*Cc];

struct WPtrs { const float* p[20]; };

// ---------------- weight folding (BN folded into linear), quad layout ----------------
__device__ __forceinline__ void foldQ(float* F, int offW, int offB,
                                      const float* W, const float* bv,
                                      const float* g, const float* be,
                                      int blk, int o, int J) {
  float gs = g[blk*64+o]*BN_SCALE_F;
  int l = o & 31, hi = o >> 5;
  for (int j = 0; j < J; j++)
    F[offW + ((j>>1)*32 + l)*4 + (j&1)*2 + hi] = W[(size_t)blk*64*J + o*J + j]*gs;
  F[offB+o] = bv[blk*64+o]*gs + be[blk*64+o];
}

__global__ void fold_kernel(WPtrs wp) {
  int blk = blockIdx.x, o = threadIdx.x;  // grid 2, block 64
  float* F = g_fold + blk*FOLD_FLOATS;
  foldQ(F, OFF_WQ1, OFF_B1,  wp.p[0],  wp.p[1],  wp.p[2],  wp.p[3],  blk, o, 3);
  // zero the padded j=3 weight slots of stage-1 quad 1
  F[OFF_WQ1 + (32 + (o&31))*4 + 2 + (o>>5)] = 0.f;
  foldQ(F, OFF_WQ2, OFF_B2,  wp.p[4],  wp.p[5],  wp.p[6],  wp.p[7],  blk, o, 64);
  foldQ(F, OFF_AQ1, OFF_AB1, wp.p[8],  wp.p[9],  wp.p[10], wp.p[11], blk, o, 64);
  foldQ(F, OFF_AQ2, OFF_AB2, wp.p[12], wp.p[13], wp.p[14], wp.p[15], blk, o, 64);
  foldQ(F, OFF_DQ,  OFF_DB,  wp.p[16], wp.p[17], wp.p[18], wp.p[19], blk, o, 64);
}

// ---------------- pack p [B,3,N] -> float4 [B*N] ----------------
__global__ void pack_p_kernel(const float* __restrict__ p) {
  int t = blockIdx.x*blockDim.x + threadIdx.x;
  if (t < Bc*Nc) {
    int b = t >> 13, n = t & (Nc-1);
    const float* pb = p + (size_t)b*3*Nc;
    g_p4[t] = make_float4(pb[n], pb[Nc+n], pb[2*Nc+n], 0.f);
  }
}

// ---------------- transpose x [B,C,N] -> [B,N,C] ----------------
__global__ void trans_x_kernel(const float* __restrict__ x) {
  __shared__ float t[32][33];
  int b = blockIdx.z;
  int n0 = blockIdx.x*32, c0 = blockIdx.y*32;
  int tx = threadIdx.x, ty = threadIdx.y;  // 32x8
  for (int i = ty; i < 32; i += 8)
    t[i][tx] = x[(size_t)b*Cc*Nc + (size_t)(c0+i)*Nc + n0 + tx];
  __syncthreads();
  for (int i = ty; i < 32; i += 8)
    g_xA[(size_t)b*Nc*Cc + (size_t)(n0+i)*Cc + c0 + tx] = t[tx][i];
}

// ---------------- helpers ----------------
__device__ __forceinline__ void fma16(float wx, float wy,
                                      float4 va, float4 vb, float4 vc, float4 vd,
                                      float a0[16], float a1[16]) {
  a0[0]  = fmaf(wx, va.x, a0[0]);  a0[1]  = fmaf(wx, va.y, a0[1]);
  a0[2]  = fmaf(wx, va.z, a0[2]);  a0[3]  = fmaf(wx, va.w, a0[3]);
  a0[4]  = fmaf(wx, vb.x, a0[4]);  a0[5]  = fmaf(wx, vb.y, a0[5]);
  a0[6]  = fmaf(wx, vb.z, a0[6]);  a0[7]  = fmaf(wx, vb.w, a0[7]);
  a0[8]  = fmaf(wx, vc.x, a0[8]);  a0[9]  = fmaf(wx, vc.y, a0[9]);
  a0[10] = fmaf(wx, vc.z, a0[10]); a0[11] = fmaf(wx, vc.w, a0[11]);
  a0[12] = fmaf(wx, vd.x, a0[12]); a0[13] = fmaf(wx, vd.y, a0[13]);
  a0[14] = fmaf(wx, vd.z, a0[14]); a0[15] = fmaf(wx, vd.w, a0[15]);
  a1[0]  = fmaf(wy, va.x, a1[0]);  a1[1]  = fmaf(wy, va.y, a1[1]);
  a1[2]  = fmaf(wy, va.z, a1[2]);  a1[3]  = fmaf(wy, va.w, a1[3]);
  a1[4]  = fmaf(wy, vb.x, a1[4]);  a1[5]  = fmaf(wy, vb.y, a1[5]);
  a1[6]  = fmaf(wy, vb.z, a1[6]);  a1[7]  = fmaf(wy, vb.w, a1[7]);
  a1[8]  = fmaf(wy, vc.x, a1[8]);  a1[9]  = fmaf(wy, vc.y, a1[9]);
  a1[10] = fmaf(wy, vc.z, a1[10]); a1[11] = fmaf(wy, vc.w, a1[11]);
  a1[12] = fmaf(wy, vd.x, a1[12]); a1[13] = fmaf(wy, vd.y, a1[13]);
  a1[14] = fmaf(wy, vd.z, a1[14]); a1[15] = fmaf(wy, vd.w, a1[15]);
}

// matvec, weights via LDG.128 quads (L1-resident), v via broadcast LDS.128
template<int QUADS>
__device__ __forceinline__ void mvQ(const float4* __restrict__ Wq,
                                    const float* __restrict__ Bv,
                                    const float* __restrict__ v, int lane,
                                    float a0[16], float a1[16]) {
  float b0 = __ldg(Bv + lane), b1 = __ldg(Bv + lane + 32);
#pragma unroll
  for (int k = 0; k < 16; k++) { a0[k] = b0; a1[k] = b1; }
#pragma unroll 2
  for (int q = 0; q < QUADS; q++) {
    float4 w = __ldg(Wq + q*32 + lane);
    const float* ve = v + (2*q)*VSTRIDE;
    {
      float4 va = *(const float4*)(ve);
      float4 vb = *(const float4*)(ve + 4);
      float4 vc = *(const float4*)(ve + 8);
      float4 vd = *(const float4*)(ve + 12);
      fma16(w.x, w.y, va, vb, vc, vd, a0, a1);
    }
    {
      const float* vo = ve + VSTRIDE;
      float4 va = *(const float4*)(vo);
      float4 vb = *(const float4*)(vo + 4);
      float4 vc = *(const float4*)(vo + 8);
      float4 vd = *(const float4*)(vo + 12);
      fma16(w.z, w.w, va, vb, vc, vd, a0, a1);
    }
  }
}

__device__ __forceinline__ void store_v(float* v, int lane,
                                        const float a0[16], const float a1[16]) {
  float* r0 = v + lane*VSTRIDE;
  float* r1 = v + (lane+32)*VSTRIDE;
#pragma unroll
  for (int kq = 0; kq < 4; kq++) {
    *(float4*)(r0 + kq*4) = make_float4(a0[kq*4], a0[kq*4+1], a0[kq*4+2], a0[kq*4+3]);
    *(float4*)(r1 + kq*4) = make_float4(a1[kq*4], a1[kq*4+1], a1[kq*4+2], a1[kq*4+3]);
  }
}

// ---------------- fused PT block: warp-per-point ----------------
__global__ void __launch_bounds__(768, 1) trblock_kernel(
    const int* __restrict__ idx, int blk, int finalOut, float* __restrict__ dout) {
  const float* __restrict__ xin = blk ? g_xB : g_xA;
  extern __shared__ float S[];
  int tid = threadIdx.x, wid = tid >> 5, lane = tid & 31;

  const float* F = g_fold + blk*FOLD_FLOATS;
  const float4* WQ1 = (const float4*)(F + OFF_WQ1);
  const float4* WQ2 = (const float4*)(F + OFF_WQ2);
  const float4* AQ1 = (const float4*)(F + OFF_AQ1);
  const float4* AQ2 = (const float4*)(F + OFF_AQ2);
  const float4* DQ  = (const float4*)(F + OFF_DQ);

  float* v  = S + wid*VWARP;
  int*   nb = (int*)(S + NB_OFF) + wid*16;

  for (int pt = blockIdx.x*NWARPS + wid; pt < Bc*Nc; pt += gridDim.x*NWARPS) {
    int b = pt >> 13;
    __syncwarp();
    if (lane < 16) {
      int j = idx[(size_t)pt*Kc + lane];
      nb[lane] = j;
      float4 pq = g_p4[pt];
      float4 pn = g_p4[(b << 13) + j];
      v[0*VSTRIDE + lane] = pq.x - pn.x;
      v[1*VSTRIDE + lane] = pq.y - pn.y;
      v[2*VSTRIDE + lane] = pq.z - pn.z;
      v[3*VSTRIDE + lane] = 0.f;   // padded j=3 row (zero weight)
    }
    __syncwarp();

    float a0[16], a1[16];
    // ---- delta layer1 (3 -> 64, padded to 4) + relu ----
    mvQ<2>(WQ1, F + OFF_B1, v, lane, a0, a1);
#pragma unroll
    for (int k = 0; k < 16; k++) { a0[k] = fmaxf(a0[k], 0.f); a1[k] = fmaxf(a1[k], 0.f); }
    __syncwarp(); store_v(v, lane, a0, a1); __syncwarp();

    // ---- delta layer2 (64 -> 64), no relu -> pe ----
    mvQ<32>(WQ2, F + OFF_B2, v, lane, a0, a1);

    // ---- u = gx + pe (gather of transposed x, coalesced, L2-resident) ----
    {
      const float* xb = xin + (((size_t)b) << 13)*Cc;
#pragma unroll
      for (int k = 0; k < 16; k++) {
        int j = nb[k];
        a0[k] += xb[(size_t)j*Cc + lane];
        a1[k] += xb[(size_t)j*Cc + lane + 32];
      }
    }
    __syncwarp(); store_v(v, lane, a0, a1); __syncwarp();

    // ---- alpha layer1 + relu ----
    mvQ<32>(AQ1, F + OFF_AB1, v, lane, a0, a1);
#pragma unroll
    for (int k = 0; k < 16; k++) { a0[k] = fmaxf(a0[k], 0.f); a1[k] = fmaxf(a1[k], 0.f); }
    __syncwarp(); store_v(v, lane, a0, a1); __syncwarp();

    // ---- alpha layer2; relu fused into max over K ----
    mvQ<32>(AQ2, F + OFF_AB2, v, lane, a0, a1);
    float m0 = 0.f, m1 = 0.f;
#pragma unroll
    for (int k = 0; k < 16; k++) { m0 = fmaxf(m0, a0[k]); m1 = fmaxf(m1, a1[k]); }

    // ---- down projection (64 -> 64) + residual ----
    __syncwarp();
    v[lane*VSTRIDE]      = m0;
    v[(lane+32)*VSTRIDE] = m1;
    __syncwarp();
    float o0 = __ldg(F + OFF_DB + lane), o1 = __ldg(F + OFF_DB + lane + 32);
#pragma unroll 4
    for (int q = 0; q < 32; q++) {
      float4 w = __ldg(DQ + q*32 + lane);
      float y0 = v[(2*q)*VSTRIDE];
      float y1 = v[(2*q+1)*VSTRIDE];
      o0 = fmaf(w.x, y0, fmaf(w.z, y1, o0));
      o1 = fmaf(w.y, y0, fmaf(w.w, y1, o1));
    }
    const float* xr = xin + (size_t)pt*Cc;
    o0 += xr[lane];
    o1 += xr[lane + 32];

    int n = pt & (Nc-1);
    if (finalOut) {
      dout[(size_t)b*Cc*Nc + (size_t)lane*Nc + n]      = o0;
      dout[(size_t)b*Cc*Nc + (size_t)(lane+32)*Nc + n] = o1;
    } else {
      float* xo = g_xB + (size_t)pt*Cc;
      xo[lane]      = o0;
      xo[lane + 32] = o1;
    }
  }
}

// ---------------- launch ----------------
extern "C" void kernel_launch(void* const* d_in, const int* in_sizes, int n_in,
                              void* d_out, int out_size) {
  const float* p  = (const float*)d_in[0];
  const float* x  = (const float*)d_in[1];
  const int*  idx = (const int*)d_in[2];
  WPtrs w;
  for (int i = 0; i < 20; i++) w.p[i] = (const float*)d_in[3 + i];

  fold_kernel<<<2, 64>>>(w);
  pack_p_kernel<<<(Bc*Nc + 255)/256, 256>>>(p);
  trans_x_kernel<<<dim3(Nc/32, Cc/32, Bc), dim3(32, 8)>>>(x);

  size_t smem = SMEM_FLOATS * sizeof(float);
  cudaFuncSetAttribute(trblock_kernel, cudaFuncAttributeMaxDynamicSharedMemorySize, (int)smem);

  float* dout = (float*)d_out;
  trblock_kernel<<<148, 768, smem>>>(idx, 0, 0, nullptr);
  trblock_kernel<<<148, 768, smem>>>(idx, 1, 1, dout + (size_t)Bc*3*Nc);

  // first output: p passes through unchanged
  cudaMemcpyAsync(d_out, d_in[0], (size_t)Bc*3*Nc*sizeof(float),
                  cudaMemcpyDeviceToDevice);
}

// round 5
// speedup vs baseline: 2.5259x; 1.0503x over previous
#include <cuda_runtime.h>

#define Bc 4
#define Nc 8192
#define Cc 64
#define Kc 16
#define BN_SCALE_F 0.9999950000374997f

// folded-weight slab (floats), per block. Matvec weights in "quad" layout:
// float4 at ((j>>1)*32 + lane)*4 = { W[lane][j], W[lane+32][j], W[lane][j+1], W[lane+32][j+1] }
#define OFF_WQ1  0        // 2 quads * 32 * 4 = 256 (J=3 + zero pad)
#define OFF_B1   256
#define OFF_WQ2  320      // 32 quads * 128 = 4096
#define OFF_B2   4416
#define OFF_AQ1  4480
#define OFF_AB1  8576
#define OFF_AQ2  8640
#define OFF_AB2  12736
#define OFF_DQ   12800
#define OFF_DB   16896
#define FOLD_FLOATS 16960

#define VSTRIDE 20
#define VWARP   (64*VSTRIDE)               // 1280 floats per warp
#define NWARPS  24
#define VOFF    FOLD_FLOATS                // v buffers after weight slab
#define NB_OFF  (VOFF + NWARPS*VWARP)      // 47680
#define SMEM_FLOATS (NB_OFF + NWARPS*16)   // 48064 floats = 192.3 KB

__device__ float  g_fold[2*FOLD_FLOATS];
__device__ float4 g_p4[Bc*Nc];
__device__ float  g_xA[Bc*Nc*Cc];
__device__ float  g_xB[Bc*Nc*Cc];

struct WPtrs { const float* p[20]; };

// ---------------- weight folding (BN folded into linear), quad layout ----------------
__device__ __forceinline__ void foldQ(float* F, int offW, int offB,
                                      const float* W, const float* bv,
                                      const float* g, const float* be,
                                      int blk, int o, int J) {
  float gs = g[blk*64+o]*BN_SCALE_F;
  int l = o & 31, hi = o >> 5;
  for (int j = 0; j < J; j++)
    F[offW + ((j>>1)*32 + l)*4 + (j&1)*2 + hi] = W[(size_t)blk*64*J + o*J + j]*gs;
  F[offB+o] = bv[blk*64+o]*gs + be[blk*64+o];
}

__global__ void fold_kernel(WPtrs wp) {
  int blk = blockIdx.x, o = threadIdx.x;  // grid 2, block 64
  float* F = g_fold + blk*FOLD_FLOATS;
  foldQ(F, OFF_WQ1, OFF_B1,  wp.p[0],  wp.p[1],  wp.p[2],  wp.p[3],  blk, o, 3);
  // zero the padded j=3 weight slots of stage-1 quad 1
  F[OFF_WQ1 + (32 + (o&31))*4 + 2 + (o>>5)] = 0.f;
  foldQ(F, OFF_WQ2, OFF_B2,  wp.p[4],  wp.p[5],  wp.p[6],  wp.p[7],  blk, o, 64);
  foldQ(F, OFF_AQ1, OFF_AB1, wp.p[8],  wp.p[9],  wp.p[10], wp.p[11], blk, o, 64);
  foldQ(F, OFF_AQ2, OFF_AB2, wp.p[12], wp.p[13], wp.p[14], wp.p[15], blk, o, 64);
  foldQ(F, OFF_DQ,  OFF_DB,  wp.p[16], wp.p[17], wp.p[18], wp.p[19], blk, o, 64);
}

// ---------------- pack p [B,3,N] -> float4 [B*N] ----------------
__global__ void pack_p_kernel(const float* __restrict__ p) {
  int t = blockIdx.x*blockDim.x + threadIdx.x;
  if (t < Bc*Nc) {
    int b = t >> 13, n = t & (Nc-1);
    const float* pb = p + (size_t)b*3*Nc;
    g_p4[t] = make_float4(pb[n], pb[Nc+n], pb[2*Nc+n], 0.f);
  }
}

// ---------------- transpose x [B,C,N] -> [B,N,C] ----------------
__global__ void trans_x_kernel(const float* __restrict__ x) {
  __shared__ float t[32][33];
  int b = blockIdx.z;
  int n0 = blockIdx.x*32, c0 = blockIdx.y*32;
  int tx = threadIdx.x, ty = threadIdx.y;  // 32x8
  for (int i = ty; i < 32; i += 8)
    t[i][tx] = x[(size_t)b*Cc*Nc + (size_t)(c0+i)*Nc + n0 + tx];
  __syncthreads();
  for (int i = ty; i < 32; i += 8)
    g_xA[(size_t)b*Nc*Cc + (size_t)(n0+i)*Cc + c0 + tx] = t[tx][i];
}

// ---------------- helpers ----------------
__device__ __forceinline__ void fma16(float wx, float wy,
                                      float4 va, float4 vb, float4 vc, float4 vd,
                                      float a0[16], float a1[16]) {
  a0[0]  = fmaf(wx, va.x, a0[0]);  a0[1]  = fmaf(wx, va.y, a0[1]);
  a0[2]  = fmaf(wx, va.z, a0[2]);  a0[3]  = fmaf(wx, va.w, a0[3]);
  a0[4]  = fmaf(wx, vb.x, a0[4]);  a0[5]  = fmaf(wx, vb.y, a0[5]);
  a0[6]  = fmaf(wx, vb.z, a0[6]);  a0[7]  = fmaf(wx, vb.w, a0[7]);
  a0[8]  = fmaf(wx, vc.x, a0[8]);  a0[9]  = fmaf(wx, vc.y, a0[9]);
  a0[10] = fmaf(wx, vc.z, a0[10]); a0[11] = fmaf(wx, vc.w, a0[11]);
  a0[12] = fmaf(wx, vd.x, a0[12]); a0[13] = fmaf(wx, vd.y, a0[13]);
  a0[14] = fmaf(wx, vd.z, a0[14]); a0[15] = fmaf(wx, vd.w, a0[15]);
  a1[0]  = fmaf(wy, va.x, a1[0]);  a1[1]  = fmaf(wy, va.y, a1[1]);
  a1[2]  = fmaf(wy, va.z, a1[2]);  a1[3]  = fmaf(wy, va.w, a1[3]);
  a1[4]  = fmaf(wy, vb.x, a1[4]);  a1[5]  = fmaf(wy, vb.y, a1[5]);
  a1[6]  = fmaf(wy, vb.z, a1[6]);  a1[7]  = fmaf(wy, vb.w, a1[7]);
  a1[8]  = fmaf(wy, vc.x, a1[8]);  a1[9]  = fmaf(wy, vc.y, a1[9]);
  a1[10] = fmaf(wy, vc.z, a1[10]); a1[11] = fmaf(wy, vc.w, a1[11]);
  a1[12] = fmaf(wy, vd.x, a1[12]); a1[13] = fmaf(wy, vd.y, a1[13]);
  a1[14] = fmaf(wy, vd.z, a1[14]); a1[15] = fmaf(wy, vd.w, a1[15]);
}

// matvec: weights via LDS.128 quads (shared), v via broadcast LDS.128
template<int QUADS>
__device__ __forceinline__ void mvQ(const float4* __restrict__ Wq,
                                    const float* __restrict__ Bv,
                                    const float* __restrict__ v, int lane,
                                    float a0[16], float a1[16]) {
  float b0 = Bv[lane], b1 = Bv[lane + 32];
#pragma unroll
  for (int k = 0; k < 16; k++) { a0[k] = b0; a1[k] = b1; }
#pragma unroll 2
  for (int q = 0; q < QUADS; q++) {
    float4 w = Wq[q*32 + lane];
    const float* ve = v + (2*q)*VSTRIDE;
    {
      float4 va = *(const float4*)(ve);
      float4 vb = *(const float4*)(ve + 4);
      float4 vc = *(const float4*)(ve + 8);
      float4 vd = *(const float4*)(ve + 12);
      fma16(w.x, w.y, va, vb, vc, vd, a0, a1);
    }
    {
      const float* vo = ve + VSTRIDE;
      float4 va = *(const float4*)(vo);
      float4 vb = *(const float4*)(vo + 4);
      float4 vc = *(const float4*)(vo + 8);
      float4 vd = *(const float4*)(vo + 12);
      fma16(w.z, w.w, va, vb, vc, vd, a0, a1);
    }
  }
}

__device__ __forceinline__ void store_v(float* v, int lane,
                                        const float a0[16], const float a1[16]) {
  float* r0 = v + lane*VSTRIDE;
  float* r1 = v + (lane+32)*VSTRIDE;
#pragma unroll
  for (int kq = 0; kq < 4; kq++) {
    *(float4*)(r0 + kq*4) = make_float4(a0[kq*4], a0[kq*4+1], a0[kq*4+2], a0[kq*4+3]);
    *(float4*)(r1 + kq*4) = make_float4(a1[kq*4], a1[kq*4+1], a1[kq*4+2], a1[kq*4+3]);
  }
}

// ---------------- fused PT block: warp-per-point, shared weight slab ----------------
__global__ void __launch_bounds__(768, 1) trblock_kernel(
    const int* __restrict__ idx, int blk, int finalOut, float* __restrict__ dout) {
  const float* __restrict__ xin = blk ? g_xB : g_xA;
  extern __shared__ float S[];
  int tid = threadIdx.x, wid = tid >> 5, lane = tid & 31;

  // one shared copy of the folded weights for all 24 warps
  const float* F = g_fold + blk*FOLD_FLOATS;
  for (int i = tid; i < FOLD_FLOATS/4; i += 768)
    ((float4*)S)[i] = ((const float4*)F)[i];
  __syncthreads();

  const float4* WQ1 = (const float4*)(S + OFF_WQ1);
  const float4* WQ2 = (const float4*)(S + OFF_WQ2);
  const float4* AQ1 = (const float4*)(S + OFF_AQ1);
  const float4* AQ2 = (const float4*)(S + OFF_AQ2);
  const float4* DQ  = (const float4*)(S + OFF_DQ);

  float* v  = S + VOFF + wid*VWARP;
  int*   nb = (int*)(S + NB_OFF) + wid*16;

  for (int pt = blockIdx.x*NWARPS + wid; pt < Bc*Nc; pt += gridDim.x*NWARPS) {
    int b = pt >> 13;
    __syncwarp();
    if (lane < 16) {
      int j = idx[(size_t)pt*Kc + lane];
      nb[lane] = j;
      float4 pq = g_p4[pt];
      float4 pn = g_p4[(b << 13) + j];
      v[0*VSTRIDE + lane] = pq.x - pn.x;
      v[1*VSTRIDE + lane] = pq.y - pn.y;
      v[2*VSTRIDE + lane] = pq.z - pn.z;
      v[3*VSTRIDE + lane] = 0.f;   // padded j=3 row (zero weight)
    }
    __syncwarp();

    float a0[16], a1[16];
    // ---- delta layer1 (3 -> 64, padded to 4) + relu ----
    mvQ<2>(WQ1, S + OFF_B1, v, lane, a0, a1);
#pragma unroll
    for (int k = 0; k < 16; k++) { a0[k] = fmaxf(a0[k], 0.f); a1[k] = fmaxf(a1[k], 0.f); }
    __syncwarp(); store_v(v, lane, a0, a1); __syncwarp();

    // ---- delta layer2 (64 -> 64), no relu -> pe ----
    mvQ<32>(WQ2, S + OFF_B2, v, lane, a0, a1);

    // ---- u = gx + pe (gather of transposed x, coalesced, L2-resident) ----
    {
      const float* xb = xin + (((size_t)b) << 13)*Cc;
#pragma unroll
      for (int k = 0; k < 16; k++) {
        int j = nb[k];
        a0[k] += xb[(size_t)j*Cc + lane];
        a1[k] += xb[(size_t)j*Cc + lane + 32];
      }
    }
    __syncwarp(); store_v(v, lane, a0, a1); __syncwarp();

    // ---- alpha layer1 + relu ----
    mvQ<32>(AQ1, S + OFF_AB1, v, lane, a0, a1);
#pragma unroll
    for (int k = 0; k < 16; k++) { a0[k] = fmaxf(a0[k], 0.f); a1[k] = fmaxf(a1[k], 0.f); }
    __syncwarp(); store_v(v, lane, a0, a1); __syncwarp();

    // ---- alpha layer2; relu fused into max over K ----
    mvQ<32>(AQ2, S + OFF_AB2, v, lane, a0, a1);
    float m0 = 0.f, m1 = 0.f;
#pragma unroll
    for (int k = 0; k < 16; k++) { m0 = fmaxf(m0, a0[k]); m1 = fmaxf(m1, a1[k]); }

    // ---- down projection (64 -> 64) + residual ----
    __syncwarp();
    v[lane*VSTRIDE]      = m0;
    v[(lane+32)*VSTRIDE] = m1;
    __syncwarp();
    float o0 = S[OFF_DB + lane], o1 = S[OFF_DB + lane + 32];
#pragma unroll 4
    for (int q = 0; q < 32; q++) {
      float4 w = DQ[q*32 + lane];
      float y0 = v[(2*q)*VSTRIDE];
      float y1 = v[(2*q+1)*VSTRIDE];
      o0 = fmaf(w.x, y0, fmaf(w.z, y1, o0));
      o1 = fmaf(w.y, y0, fmaf(w.w, y1, o1));
    }
    const float* xr = xin + (size_t)pt*Cc;
    o0 += xr[lane];
    o1 += xr[lane + 32];

    int n = pt & (Nc-1);
    if (finalOut) {
      dout[(size_t)b*Cc*Nc + (size_t)lane*Nc + n]      = o0;
      dout[(size_t)b*Cc*Nc + (size_t)(lane+32)*Nc + n] = o1;
    } else {
      float* xo = g_xB + (size_t)pt*Cc;
      xo[lane]      = o0;
      xo[lane + 32] = o1;
    }
  }
}

// ---------------- launch ----------------
extern "C" void kernel_launch(void* const* d_in, const int* in_sizes, int n_in,
                              void* d_out, int out_size) {
  const float* p  = (const float*)d_in[0];
  const float* x  = (const float*)d_in[1];
  const int*  idx = (const int*)d_in[2];
  WPtrs w;
  for (int i = 0; i < 20; i++) w.p[i] = (const float*)d_in[3 + i];

  fold_kernel<<<2, 64>>>(w);
  pack_p_kernel<<<(Bc*Nc + 255)/256, 256>>>(p);
  trans_x_kernel<<<dim3(Nc/32, Cc/32, Bc), dim3(32, 8)>>>(x);

  size_t smem = SMEM_FLOATS * sizeof(float);
  cudaFuncSetAttribute(trblock_kernel, cudaFuncAttributeMaxDynamicSharedMemorySize, (int)smem);

  float* dout = (float*)d_out;
  trblock_kernel<<<148, 768, smem>>>(idx, 0, 0, nullptr);
  trblock_kernel<<<148, 768, smem>>>(idx, 1, 1, dout + (size_t)Bc*3*Nc);

  // first output: p passes through unchanged
  cudaMemcpyAsync(d_out, d_in[0], (size_t)Bc*3*Nc*sizeof(float),
                  cudaMemcpyDeviceToDevice);
}

// round 11
// speedup vs baseline: 3.0428x; 1.2047x over previous
#include <cuda_runtime.h>

#define Bc 4
#define Nc 8192
#define Cc 64
#define Kc 16
#define BN_SCALE_F 0.9999950000374997f

// folded-weight slab (floats), per block.
// Matvec weights (quad4 layout): float4 at (q*32 + h*16 + rg) =
//   { W[rg][2q+h], W[rg+16][2q+h], W[rg+32][2q+h], W[rg+48][2q+h] }
// Down-proj weights (pair layout): float4 at (q*32 + l) =
//   { W[l][2q], W[l+32][2q], W[l][2q+1], W[l+32][2q+1] }
#define OFF_WQ1  0        // 2 quads * 32 float4 = 256 floats (J=3 padded to 4)
#define OFF_B1   256
#define OFF_WQ2  320      // 32 quads * 128 = 4096
#define OFF_B2   4416
#define OFF_AQ1  4480
#define OFF_AB1  8576
#define OFF_AQ2  8640
#define OFF_AB2  12736
#define OFF_DQ   12800
#define OFF_DB   16896
#define FOLD_FLOATS 16960

#define VSTRIDE 20
#define VWARP   (64*VSTRIDE)               // 1280 floats per warp
#define NWARPS  8
#define VOFF    FOLD_FLOATS
#define NB_OFF  (VOFF + NWARPS*VWARP)      // 27200
#define SMEM_FLOATS (NB_OFF + NWARPS*16)   // 27328 floats = 109.3 KB -> 2 CTA/SM

__device__ float  g_fold[2*FOLD_FLOATS];
__device__ float4 g_p4[Bc*Nc];
__device__ float  g_xA[Bc*Nc*Cc];
__device__ float  g_xB[Bc*Nc*Cc];

struct WPtrs { const float* p[20]; };

// ---------------- weight folding ----------------
// quad4 layout for matvec weights
__device__ __forceinline__ void foldQuad(float* F, int offW, int offB,
                                         const float* W, const float* bv,
                                         const float* g, const float* be,
                                         int blk, int o, int J) {
  float gs = g[blk*64+o]*BN_SCALE_F;
  int rg = o & 15, t = o >> 4;
  for (int j = 0; j < J; j++)
    F[offW + ((j>>1)*32 + (j&1)*16 + rg)*4 + t] = W[(size_t)blk*64*J + o*J + j]*gs;
  F[offB+o] = bv[blk*64+o]*gs + be[blk*64+o];
}

// pair layout for down-proj
__device__ __forceinline__ void foldPair(float* F, int offW, int offB,
                                         const float* W, const float* bv,
                                         const float* g, const float* be,
                                         int blk, int o) {
  float gs = g[blk*64+o]*BN_SCALE_F;
  int l = o & 31, hi = o >> 5;
  for (int j = 0; j < 64; j++)
    F[offW + ((j>>1)*32 + l)*4 + (j&1)*2 + hi] = W[(size_t)blk*64*64 + o*64 + j]*gs;
  F[offB+o] = bv[blk*64+o]*gs + be[blk*64+o];
}

__global__ void fold_kernel(WPtrs wp) {
  int blk = blockIdx.x, o = threadIdx.x;  // grid 2, block 64
  float* F = g_fold + blk*FOLD_FLOATS;
  foldQuad(F, OFF_WQ1, OFF_B1,  wp.p[0],  wp.p[1],  wp.p[2],  wp.p[3],  blk, o, 3);
  // zero padded j=3 slot
  F[OFF_WQ1 + (48 + (o&15))*4 + (o>>4)] = 0.f;
  foldQuad(F, OFF_WQ2, OFF_B2,  wp.p[4],  wp.p[5],  wp.p[6],  wp.p[7],  blk, o, 64);
  foldQuad(F, OFF_AQ1, OFF_AB1, wp.p[8],  wp.p[9],  wp.p[10], wp.p[11], blk, o, 64);
  foldQuad(F, OFF_AQ2, OFF_AB2, wp.p[12], wp.p[13], wp.p[14], wp.p[15], blk, o, 64);
  foldPair(F, OFF_DQ,  OFF_DB,  wp.p[16], wp.p[17], wp.p[18], wp.p[19], blk, o);
}

// ---------------- pack p [B,3,N] -> float4 [B*N] ----------------
__global__ void pack_p_kernel(const float* __restrict__ p) {
  int t = blockIdx.x*blockDim.x + threadIdx.x;
  if (t < Bc*Nc) {
    int b = t >> 13, n = t & (Nc-1);
    const float* pb = p + (size_t)b*3*Nc;
    g_p4[t] = make_float4(pb[n], pb[Nc+n], pb[2*Nc+n], 0.f);
  }
}

// ---------------- transpose x [B,C,N] -> [B,N,C] ----------------
__global__ void trans_x_kernel(const float* __restrict__ x) {
  __shared__ float t[32][33];
  int b = blockIdx.z;
  int n0 = blockIdx.x*32, c0 = blockIdx.y*32;
  int tx = threadIdx.x, ty = threadIdx.y;  // 32x8
  for (int i = ty; i < 32; i += 8)
    t[i][tx] = x[(size_t)b*Cc*Nc + (size_t)(c0+i)*Nc + n0 + tx];
  __syncthreads();
  for (int i = ty; i < 32; i += 8)
    g_xA[(size_t)b*Nc*Cc + (size_t)(n0+i)*Cc + c0 + tx] = t[tx][i];
}

// ---------------- matvec: 4 rows x 8 k per lane ----------------
// acc[t*8+i] = out[rg+16t][kg*8+i]
template<int QUADS>
__device__ __forceinline__ void mvQ4(const float4* __restrict__ Wq,
                                     const float* __restrict__ Bv,
                                     const float* __restrict__ v,
                                     int rg, int kg, float acc[32]) {
#pragma unroll
  for (int t = 0; t < 4; t++) {
    float bb = Bv[rg + 16*t];
#pragma unroll
    for (int i = 0; i < 8; i++) acc[t*8+i] = bb;
  }
#pragma unroll 2
  for (int q = 0; q < QUADS; q++) {
    float4 w0 = Wq[q*32 + rg];        // j = 2q
    float4 w1 = Wq[q*32 + 16 + rg];   // j = 2q+1
    const float* ve = v + (2*q)*VSTRIDE + kg*8;
    float4 va = *(const float4*)(ve);
    float4 vb = *(const float4*)(ve + 4);
    float4 vc = *(const float4*)(ve + VSTRIDE);
    float4 vd = *(const float4*)(ve + VSTRIDE + 4);
    const float* w0f = (const float*)&w0;
    const float* w1f = (const float*)&w1;
#pragma unroll
    for (int t = 0; t < 4; t++) {
      float x0 = w0f[t], x1 = w1f[t];
      acc[t*8+0] = fmaf(x0, va.x, acc[t*8+0]);
      acc[t*8+1] = fmaf(x0, va.y, acc[t*8+1]);
      acc[t*8+2] = fmaf(x0, va.z, acc[t*8+2]);
      acc[t*8+3] = fmaf(x0, va.w, acc[t*8+3]);
      acc[t*8+4] = fmaf(x0, vb.x, acc[t*8+4]);
      acc[t*8+5] = fmaf(x0, vb.y, acc[t*8+5]);
      acc[t*8+6] = fmaf(x0, vb.z, acc[t*8+6]);
      acc[t*8+7] = fmaf(x0, vb.w, acc[t*8+7]);
      acc[t*8+0] = fmaf(x1, vc.x, acc[t*8+0]);
      acc[t*8+1] = fmaf(x1, vc.y, acc[t*8+1]);
      acc[t*8+2] = fmaf(x1, vc.z, acc[t*8+2]);
      acc[t*8+3] = fmaf(x1, vc.w, acc[t*8+3]);
      acc[t*8+4] = fmaf(x1, vd.x, acc[t*8+4]);
      acc[t*8+5] = fmaf(x1, vd.y, acc[t*8+5]);
      acc[t*8+6] = fmaf(x1, vd.z, acc[t*8+6]);
      acc[t*8+7] = fmaf(x1, vd.w, acc[t*8+7]);
    }
  }
}

template<bool RELU>
__device__ __forceinline__ void store4(float* v, int rg, int kg, const float acc[32]) {
#pragma unroll
  for (int t = 0; t < 4; t++) {
    float4 u0 = make_float4(acc[t*8+0], acc[t*8+1], acc[t*8+2], acc[t*8+3]);
    float4 u1 = make_float4(acc[t*8+4], acc[t*8+5], acc[t*8+6], acc[t*8+7]);
    if (RELU) {
      u0.x = fmaxf(u0.x, 0.f); u0.y = fmaxf(u0.y, 0.f);
      u0.z = fmaxf(u0.z, 0.f); u0.w = fmaxf(u0.w, 0.f);
      u1.x = fmaxf(u1.x, 0.f); u1.y = fmaxf(u1.y, 0.f);
      u1.z = fmaxf(u1.z, 0.f); u1.w = fmaxf(u1.w, 0.f);
    }
    float* r = v + (rg + 16*t)*VSTRIDE + kg*8;
    *(float4*)(r)     = u0;
    *(float4*)(r + 4) = u1;
  }
}

// ---------------- fused PT block ----------------
__global__ void __launch_bounds__(256, 2) trblock_kernel(
    const int* __restrict__ idx, int blk, int finalOut, float* __restrict__ dout) {
  const float* __restrict__ xin = blk ? g_xB : g_xA;
  extern __shared__ float S[];
  int tid = threadIdx.x, wid = tid >> 5, lane = tid & 31;
  int rg = lane & 15, kg = lane >> 4;

  const float* F = g_fold + blk*FOLD_FLOATS;
  for (int i = tid; i < FOLD_FLOATS/4; i += 256)
    ((float4*)S)[i] = ((const float4*)F)[i];
  __syncthreads();

  const float4* WQ1 = (const float4*)(S + OFF_WQ1);
  const float4* WQ2 = (const float4*)(S + OFF_WQ2);
  const float4* AQ1 = (const float4*)(S + OFF_AQ1);
  const float4* AQ2 = (const float4*)(S + OFF_AQ2);
  const float4* DQ  = (const float4*)(S + OFF_DQ);

  float* v  = S + VOFF + wid*VWARP;
  int*   nb = (int*)(S + NB_OFF) + wid*16;

  for (int pt = blockIdx.x*NWARPS + wid; pt < Bc*Nc; pt += gridDim.x*NWARPS) {
    int b = pt >> 13;
    __syncwarp();
    if (lane < 16) {
      int j = idx[(size_t)pt*Kc + lane];
      nb[lane] = j;
      float4 pq = g_p4[pt];
      float4 pn = g_p4[(b << 13) + j];
      v[0*VSTRIDE + lane] = pq.x - pn.x;
      v[1*VSTRIDE + lane] = pq.y - pn.y;
      v[2*VSTRIDE + lane] = pq.z - pn.z;
      v[3*VSTRIDE + lane] = 0.f;   // padded j=3 row (zero weight)
    }
    __syncwarp();

    // ---- prefetch x-gather values (consumed after delta layer2) ----
    float gx[32];
    {
      const float* xb = xin + (((size_t)b) << 13)*Cc;
      int jn[8];
#pragma unroll
      for (int i = 0; i < 8; i++) jn[i] = nb[kg*8 + i];
#pragma unroll
      for (int i = 0; i < 8; i++) {
        const float* xr = xb + (size_t)jn[i]*Cc + rg;
#pragma unroll
        for (int t = 0; t < 4; t++)
          gx[t*8+i] = xr[16*t];
      }
    }

    float acc[32];
    // ---- delta layer1 (3 -> 64, padded to 4) + relu ----
    mvQ4<2>(WQ1, S + OFF_B1, v, rg, kg, acc);
    __syncwarp(); store4<true>(v, rg, kg, acc); __syncwarp();

    // ---- delta layer2 (64 -> 64) -> pe ----
    mvQ4<32>(WQ2, S + OFF_B2, v, rg, kg, acc);

    // ---- u = gx + pe ----
#pragma unroll
    for (int i = 0; i < 32; i++) acc[i] += gx[i];
    __syncwarp(); store4<false>(v, rg, kg, acc); __syncwarp();

    // ---- alpha layer1 + relu ----
    mvQ4<32>(AQ1, S + OFF_AB1, v, rg, kg, acc);
    __syncwarp(); store4<true>(v, rg, kg, acc); __syncwarp();

    // ---- alpha layer2; relu fused into max over K ----
    mvQ4<32>(AQ2, S + OFF_AB2, v, rg, kg, acc);
    {
      float m[4];
#pragma unroll
      for (int t = 0; t < 4; t++) {
        float mm = acc[t*8];
#pragma unroll
        for (int i = 1; i < 8; i++) mm = fmaxf(mm, acc[t*8+i]);
        m[t] = mm;
      }
#pragma unroll
      for (int t = 0; t < 4; t++)
        m[t] = fmaxf(fmaxf(m[t], __shfl_xor_sync(0xffffffffu, m[t], 16)), 0.f);
      __syncwarp();
      if (kg == 0) {
#pragma unroll
        for (int t = 0; t < 4; t++)
          v[(rg + 16*t)*VSTRIDE] = m[t];
      }
      __syncwarp();
    }

    // ---- down projection (64 -> 64) + residual (pair layout) ----
    float o0 = S[OFF_DB + lane], o1 = S[OFF_DB + lane + 32];
#pragma unroll 4
    for (int q = 0; q < 32; q++) {
      float4 w = DQ[q*32 + lane];
      float y0 = v[(2*q)*VSTRIDE];
      float y1 = v[(2*q+1)*VSTRIDE];
      o0 = fmaf(w.x, y0, fmaf(w.z, y1, o0));
      o1 = fmaf(w.y, y0, fmaf(w.w, y1, o1));
    }
    const float* xr = xin + (size_t)pt*Cc;
    o0 += xr[lane];
    o1 += xr[lane + 32];

    int n = pt & (Nc-1);
    if (finalOut) {
      dout[(size_t)b*Cc*Nc + (size_t)lane*Nc + n]      = o0;
      dout[(size_t)b*Cc*Nc + (size_t)(lane+32)*Nc + n] = o1;
    } else {
      float* xo = g_xB + (size_t)pt*Cc;
      xo[lane]      = o0;
      xo[lane + 32] = o1;
    }
  }
}

// ---------------- launch ----------------
extern "C" void kernel_launch(void* const* d_in, const int* in_sizes, int n_in,
                              void* d_out, int out_size) {
  const float* p  = (const float*)d_in[0];
  const float* x  = (const float*)d_in[1];
  const int*  idx = (const int*)d_in[2];
  WPtrs w;
  for (int i = 0; i < 20; i++) w.p[i] = (const float*)d_in[3 + i];

  fold_kernel<<<2, 64>>>(w);
  pack_p_kernel<<<(Bc*Nc + 255)/256, 256>>>(p);
  trans_x_kernel<<<dim3(Nc/32, Cc/32, Bc), dim3(32, 8)>>>(x);

  size_t smem = SMEM_FLOATS * sizeof(float);
  cudaFuncSetAttribute(trblock_kernel, cudaFuncAttributeMaxDynamicSharedMemorySize, (int)smem);

  float* dout = (float*)d_out;
  trblock_kernel<<<296, 256, smem>>>(idx, 0, 0, nullptr);
  trblock_kernel<<<296, 256, smem>>>(idx, 1, 1, dout + (size_t)Bc*3*Nc);

  // first output: p passes through unchanged
  cudaMemcpyAsync(d_out, d_in[0], (size_t)Bc*3*Nc*sizeof(float),
                  cudaMemcpyDeviceToDevice);
}

// round 17
// speedup vs baseline: 6.8611x; 2.2548x over previous
#include <cuda_runtime.h>
#include <cuda_bf16.h>

#define Bc 4
#define Nc 8192
#define Cc 64
#define Kc 16
#define BN_SCALE_F 0.9999950000374997f

typedef unsigned int u32;

// smem float offsets
#define OFF_FRAG  0        // 3 layers * 32 (nt*4+kc) * 32 lanes * uint4 = 12288 floats
#define OFF_DQ    12288    // down-proj pair quads, 4096 floats
#define OFF_W1B   16384    // float4[64] {w0,w1,w2,b}
#define OFF_BIAS  16640    // [b2 | ab1 | ab2 | db] 4*64
#define OFF_Y     16896    // 8 warps * 64
#define SMEM_FLOATS 17408  // 69.6 KB

__device__ float4 g_p4[Bc*Nc];
__device__ float  g_xA[Bc*Nc*Cc];
__device__ float  g_xB[Bc*Nc*Cc];
__device__ uint4  g_frag[2*3*32*32];   // [blk][L][nt*4+kc][lane] = {bh0,bh1,bl0,bl1}
__device__ float  g_dq[2*4096];
__device__ float  g_w1b[2*256];
__device__ float  g_bias[2*256];

struct WPtrs { const float* p[20]; };

// ---------------- helpers ----------------
__device__ __forceinline__ u32 bf16x2_of(float lo, float hi) {
  u32 r; asm("cvt.rn.bf16x2.f32 %0, %1, %2;" : "=r"(r) : "f"(hi), "f"(lo));
  return r;
}
// split pair (x,y) into hi bf16x2 and lo bf16x2 (residual)
__device__ __forceinline__ void split2(float x, float y, u32& hi, u32& lo) {
  u32 h = bf16x2_of(x, y);
  float hx = __uint_as_float(h << 16);
  float hy = __uint_as_float(h & 0xffff0000u);
  hi = h;
  lo = bf16x2_of(x - hx, y - hy);
}

__device__ __forceinline__ void mma_bf16(float d[4], const u32* a, u32 b0, u32 b1) {
  asm volatile("mma.sync.aligned.m16n8k16.row.col.f32.bf16.bf16.f32 "
      "{%0,%1,%2,%3},{%4,%5,%6,%7},{%8,%9},{%0,%1,%2,%3};"
      : "+f"(d[0]), "+f"(d[1]), "+f"(d[2]), "+f"(d[3])
      : "r"(a[0]), "r"(a[1]), "r"(a[2]), "r"(a[3]), "r"(b0), "r"(b1));
}

// one 16x64x64 layer: D[8 n-tiles] from A (hi/lo) and precomputed B frags
__device__ __forceinline__ void run_layer(const uint4* __restrict__ WF,
                                          const u32 Ah[16], const u32 Al[16],
                                          float4 D[8], int lane) {
#pragma unroll
  for (int nt = 0; nt < 8; nt++) {
    float d[4] = {0.f, 0.f, 0.f, 0.f};
#pragma unroll
    for (int kc = 0; kc < 4; kc++) {
      uint4 f = WF[(nt*4 + kc)*32 + lane];
      mma_bf16(d, Ah + kc*4, f.x, f.y);   // Ah * Bh
      mma_bf16(d, Al + kc*4, f.x, f.y);   // Al * Bh
      mma_bf16(d, Ah + kc*4, f.z, f.w);   // Ah * Bl
    }
    D[nt] = make_float4(d[0], d[1], d[2], d[3]);
  }
}

// ---------------- prep kernels ----------------
__global__ void fold_kernel(WPtrs wp) {
  int blk = blockIdx.x, tid = threadIdx.x;   // grid 2, block 128
  // B fragments for the three 64x64 GEMM layers (delta2, alpha1, alpha2)
  for (int e = tid; e < 3*1024; e += 128) {
    int L = e >> 10, rem = e & 1023;
    int ntkc = rem >> 5, lane = rem & 31;
    int kc = ntkc & 3, nt = ntkc >> 2;
    int c = lane & 3, r = lane >> 2;
    int n = 8*nt + r;
    const float* W  = wp.p[4 + 4*L];
    const float* g  = wp.p[6 + 4*L];
    float gs = g[blk*64 + n]*BN_SCALE_F;
    const float* Wr = W + (size_t)blk*4096 + n*64;
    float w00 = Wr[16*kc + 2*c]     * gs;
    float w01 = Wr[16*kc + 2*c + 1] * gs;
    float w10 = Wr[16*kc + 2*c + 8] * gs;
    float w11 = Wr[16*kc + 2*c + 9] * gs;
    uint4 f;
    split2(w00, w01, f.x, f.z);
    split2(w10, w11, f.y, f.w);
    g_frag[(blk*3 + L)*1024 + ntkc*32 + lane] = f;
  }
  if (tid < 64) {
    int o = tid;
    // biases for the 3 GEMM layers
    for (int L = 0; L < 3; L++) {
      float gs = wp.p[6+4*L][blk*64+o]*BN_SCALE_F;
      g_bias[blk*256 + L*64 + o] = wp.p[5+4*L][blk*64+o]*gs + wp.p[7+4*L][blk*64+o];
    }
    // delta1 (3 -> 64)
    {
      float gs = wp.p[2][blk*64+o]*BN_SCALE_F;
      g_w1b[blk*256 + o*4 + 0] = wp.p[0][blk*192 + o*3+0]*gs;
      g_w1b[blk*256 + o*4 + 1] = wp.p[0][blk*192 + o*3+1]*gs;
      g_w1b[blk*256 + o*4 + 2] = wp.p[0][blk*192 + o*3+2]*gs;
      g_w1b[blk*256 + o*4 + 3] = wp.p[1][blk*64+o]*gs + wp.p[3][blk*64+o];
    }
    // down-proj pair quads + bias
    {
      float gs = wp.p[18][blk*64+o]*BN_SCALE_F;
      int l = o & 31, hi = o >> 5;
      for (int j = 0; j < 64; j++)
        g_dq[blk*4096 + ((j>>1)*32 + l)*4 + (j&1)*2 + hi] =
            wp.p[16][(size_t)blk*4096 + o*64 + j]*gs;
      g_bias[blk*256 + 192 + o] = wp.p[17][blk*64+o]*gs + wp.p[19][blk*64+o];
    }
  }
}

__global__ void pack_p_kernel(const float* __restrict__ p) {
  int t = blockIdx.x*blockDim.x + threadIdx.x;
  if (t < Bc*Nc) {
    int b = t >> 13, n = t & (Nc-1);
    const float* pb = p + (size_t)b*3*Nc;
    g_p4[t] = make_float4(pb[n], pb[Nc+n], pb[2*Nc+n], 0.f);
  }
}

__global__ void trans_x_kernel(const float* __restrict__ x) {
  __shared__ float t[32][33];
  int b = blockIdx.z;
  int n0 = blockIdx.x*32, c0 = blockIdx.y*32;
  int tx = threadIdx.x, ty = threadIdx.y;  // 32x8
  for (int i = ty; i < 32; i += 8)
    t[i][tx] = x[(size_t)b*Cc*Nc + (size_t)(c0+i)*Nc + n0 + tx];
  __syncthreads();
  for (int i = ty; i < 32; i += 8)
    g_xA[(size_t)b*Nc*Cc + (size_t)(n0+i)*Cc + c0 + tx] = t[tx][i];
}

// ---------------- fused PT block via mma.sync ----------------
__global__ void __launch_bounds__(256, 2) trblock_mma_kernel(
    const int* __restrict__ idx, int blk, int finalOut, float* __restrict__ dout) {
  const float* __restrict__ xin = blk ? g_xB : g_xA;
  extern __shared__ float S[];
  int tid = threadIdx.x, wid = tid >> 5, lane = tid & 31;
  int c = lane & 3, r = lane >> 2;

  // stage weights into smem
  {
    const uint4* gf = g_frag + blk*3*1024;
    uint4* sf = (uint4*)(S + OFF_FRAG);
    for (int i = tid; i < 3*1024; i += 256) sf[i] = gf[i];
    const float4* gd = (const float4*)(g_dq + blk*4096);
    float4* sd = (float4*)(S + OFF_DQ);
    for (int i = tid; i < 1024; i += 256) sd[i] = gd[i];
    if (tid < 64) {
      ((float4*)(S + OFF_W1B))[tid] = ((const float4*)(g_w1b + blk*256))[tid];
      ((float4*)(S + OFF_BIAS))[tid] = ((const float4*)(g_bias + blk*256))[tid];
    }
  }
  __syncthreads();

  const uint4* WF0 = (const uint4*)(S + OFF_FRAG);
  const uint4* WF1 = WF0 + 1024;
  const uint4* WF2 = WF0 + 2048;
  const float4* W1B = (const float4*)(S + OFF_W1B);
  const float4* DQ  = (const float4*)(S + OFF_DQ);
  float* Y = S + OFF_Y + wid*64;

  for (int pt = blockIdx.x*8 + wid; pt < Bc*Nc; pt += gridDim.x*8) {
    int b = pt >> 13;
    // neighbor rows r and r+8 for this lane
    int j0 = idx[pt*Kc + r];
    int j1 = idx[pt*Kc + r + 8];
    int gj0 = (b << 13) + j0;
    int gj1 = (b << 13) + j1;

    u32 Ah[16], Al[16];
    // ---- delta1 (3 -> 64) scalar + relu, packed into A fragments ----
    {
      float4 pq = g_p4[pt];
      float4 q0 = g_p4[gj0], q1 = g_p4[gj1];
      float x0 = pq.x - q0.x, y0 = pq.y - q0.y, z0 = pq.z - q0.z;
      float x1 = pq.x - q1.x, y1 = pq.y - q1.y, z1 = pq.z - q1.z;
#pragma unroll
      for (int kc = 0; kc < 4; kc++) {
        int f0 = 16*kc + 2*c;
        float4 wA = W1B[f0],     wB = W1B[f0+1];
        float h00 = fmaxf(fmaf(wA.x,x0, fmaf(wA.y,y0, fmaf(wA.z,z0, wA.w))), 0.f);
        float h01 = fmaxf(fmaf(wB.x,x0, fmaf(wB.y,y0, fmaf(wB.z,z0, wB.w))), 0.f);
        float h10 = fmaxf(fmaf(wA.x,x1, fmaf(wA.y,y1, fmaf(wA.z,z1, wA.w))), 0.f);
        float h11 = fmaxf(fmaf(wB.x,x1, fmaf(wB.y,y1, fmaf(wB.z,z1, wB.w))), 0.f);
        split2(h00, h01, Ah[kc*4+0], Al[kc*4+0]);
        split2(h10, h11, Ah[kc*4+1], Al[kc*4+1]);
        float4 wC = W1B[f0+8],   wD = W1B[f0+9];
        float h20 = fmaxf(fmaf(wC.x,x0, fmaf(wC.y,y0, fmaf(wC.z,z0, wC.w))), 0.f);
        float h21 = fmaxf(fmaf(wD.x,x0, fmaf(wD.y,y0, fmaf(wD.z,z0, wD.w))), 0.f);
        float h30 = fmaxf(fmaf(wC.x,x1, fmaf(wC.y,y1, fmaf(wC.z,z1, wC.w))), 0.f);
        float h31 = fmaxf(fmaf(wD.x,x1, fmaf(wD.y,y1, fmaf(wD.z,z1, wD.w))), 0.f);
        split2(h20, h21, Ah[kc*4+2], Al[kc*4+2]);
        split2(h30, h31, Ah[kc*4+3], Al[kc*4+3]);
      }
    }

    float4 D[8];
    // ---- delta2 (64 -> 64) ----
    run_layer(WF0, Ah, Al, D, lane);
    // epilogue: u = pe + b2 + gx
    {
      const float* xb0 = xin + (size_t)gj0*Cc;
      const float* xb1 = xin + (size_t)gj1*Cc;
      const float* bb = S + OFF_BIAS;
#pragma unroll
      for (int nt = 0; nt < 8; nt++) {
        int f = 8*nt + 2*c;
        float2 bv = *(const float2*)(bb + f);
        float2 g0 = *(const float2*)(xb0 + f);
        float2 g1 = *(const float2*)(xb1 + f);
        D[nt].x += bv.x + g0.x;  D[nt].y += bv.y + g0.y;
        D[nt].z += bv.x + g1.x;  D[nt].w += bv.y + g1.y;
      }
#pragma unroll
      for (int m = 0; m < 4; m++) {
        split2(D[2*m].x,   D[2*m].y,   Ah[m*4+0], Al[m*4+0]);
        split2(D[2*m].z,   D[2*m].w,   Ah[m*4+1], Al[m*4+1]);
        split2(D[2*m+1].x, D[2*m+1].y, Ah[m*4+2], Al[m*4+2]);
        split2(D[2*m+1].z, D[2*m+1].w, Ah[m*4+3], Al[m*4+3]);
      }
    }

    // ---- alpha1 (64 -> 64) + relu ----
    run_layer(WF1, Ah, Al, D, lane);
    {
      const float* bb = S + OFF_BIAS + 64;
#pragma unroll
      for (int nt = 0; nt < 8; nt++) {
        int f = 8*nt + 2*c;
        float2 bv = *(const float2*)(bb + f);
        D[nt].x = fmaxf(D[nt].x + bv.x, 0.f);
        D[nt].y = fmaxf(D[nt].y + bv.y, 0.f);
        D[nt].z = fmaxf(D[nt].z + bv.x, 0.f);
        D[nt].w = fmaxf(D[nt].w + bv.y, 0.f);
      }
#pragma unroll
      for (int m = 0; m < 4; m++) {
        split2(D[2*m].x,   D[2*m].y,   Ah[m*4+0], Al[m*4+0]);
        split2(D[2*m].z,   D[2*m].w,   Ah[m*4+1], Al[m*4+1]);
        split2(D[2*m+1].x, D[2*m+1].y, Ah[m*4+2], Al[m*4+2]);
        split2(D[2*m+1].z, D[2*m+1].w, Ah[m*4+3], Al[m*4+3]);
      }
    }

    // ---- alpha2 (64 -> 64); max over the 16 neighbors, relu ----
    run_layer(WF2, Ah, Al, D, lane);
    __syncwarp();
    {
      const float* bb = S + OFF_BIAS + 128;
#pragma unroll
      for (int nt = 0; nt < 8; nt++) {
        int f = 8*nt + 2*c;
        float2 bv = *(const float2*)(bb + f);
        float m0 = fmaxf(D[nt].x + bv.x, D[nt].z + bv.x);
        float m1 = fmaxf(D[nt].y + bv.y, D[nt].w + bv.y);
        m0 = fmaxf(m0, __shfl_xor_sync(0xffffffffu, m0, 4));
        m1 = fmaxf(m1, __shfl_xor_sync(0xffffffffu, m1, 4));
        m0 = fmaxf(m0, __shfl_xor_sync(0xffffffffu, m0, 8));
        m1 = fmaxf(m1, __shfl_xor_sync(0xffffffffu, m1, 8));
        m0 = fmaxf(m0, __shfl_xor_sync(0xffffffffu, m0, 16));
        m1 = fmaxf(m1, __shfl_xor_sync(0xffffffffu, m1, 16));
        if (r == 0) {
          Y[f]   = fmaxf(m0, 0.f);
          Y[f+1] = fmaxf(m1, 0.f);
        }
      }
    }
    __syncwarp();

    // ---- down projection (64 -> 64) + residual ----
    float o0 = S[OFF_BIAS + 192 + lane], o1 = S[OFF_BIAS + 192 + lane + 32];
#pragma unroll 4
    for (int q = 0; q < 32; q++) {
      float4 w = DQ[q*32 + lane];
      float2 y2 = *(const float2*)(Y + 2*q);
      o0 = fmaf(w.x, y2.x, fmaf(w.z, y2.y, o0));
      o1 = fmaf(w.y, y2.x, fmaf(w.w, y2.y, o1));
    }
    const float* xr = xin + (size_t)pt*Cc;
    o0 += xr[lane];
    o1 += xr[lane + 32];
    __syncwarp();

    int n = pt & (Nc-1);
    if (finalOut) {
      dout[(size_t)b*Cc*Nc + (size_t)lane*Nc + n]      = o0;
      dout[(size_t)b*Cc*Nc + (size_t)(lane+32)*Nc + n] = o1;
    } else {
      float* xo = g_xB + (size_t)pt*Cc;
      xo[lane]      = o0;
      xo[lane + 32] = o1;
    }
  }
}

// ---------------- launch ----------------
extern "C" void kernel_launch(void* const* d_in, const int* in_sizes, int n_in,
                              void* d_out, int out_size) {
  const float* p  = (const float*)d_in[0];
  const float* x  = (const float*)d_in[1];
  const int*  idx = (const int*)d_in[2];
  WPtrs w;
  for (int i = 0; i < 20; i++) w.p[i] = (const float*)d_in[3 + i];

  fold_kernel<<<2, 128>>>(w);
  pack_p_kernel<<<(Bc*Nc + 255)/256, 256>>>(p);
  trans_x_kernel<<<dim3(Nc/32, Cc/32, Bc), dim3(32, 8)>>>(x);

  size_t smem = SMEM_FLOATS * sizeof(float);
  cudaFuncSetAttribute(trblock_mma_kernel, cudaFuncAttributeMaxDynamicSharedMemorySize, (int)smem);

  float* dout = (float*)d_out;
  trblock_mma_kernel<<<296, 256, smem>>>(idx, 0, 0, nullptr);
  trblock_mma_kernel<<<296, 256, smem>>>(idx, 1, 1, dout + (size_t)Bc*3*Nc);

  // first output: p passes through unchanged
  cudaMemcpyAsync(d_out, d_in[0], (size_t)Bc*3*Nc*sizeof(float),
                  cudaMemcpyDeviceToDevice);
}